// round 14
// baseline (speedup 1.0000x reference)
#include <cuda_runtime.h>

// ---------------------------------------------------------------------------
// TensoRF slim renderer, v13 — smem-resident fp32 line textures.
//  prep: combined 128B fp32 texels g_tex[i][HW][32ch] (ch0-7 density, basis
//        weights folded into LINE texture; ch8-31 appearance). Line texels
//        in the SAME array at LTEX_OFF.
//  render: CTA = 1024 threads = 4 rays, ONE CTA/SM (210KB dynamic smem),
//          32 warps/SM. Whole fp32 line texture (3*G texels, 115KB) is
//          copied to smem once per CTA; tap reads become conflict-free
//          broadcast LDS.128 (128B data vs 512B via LDG) — L1 data volume
//          drops from 4.6KB/pt to ~2.4KB/pt with zero precision change.
//    lane = corner*8 + slot. Per point/plane: 1 broadcast LDS.128 record +
//    1 dense corner LDG.128 + 2 tap LDS.128; packed f32x2 math; rows 0-2
//    via register appw; sigma via add2 on density lanes; 6-shuffle
//    butterfly reduce. Then per-ray alpha(-expm1) + product scan + reduce.
// ---------------------------------------------------------------------------

#define MAXG  320
#define MAXHW (MAXG * MAXG)
#define LTEX_OFF (3ull * MAXHW * 8)          // float4 units

__device__ float4 g_tex[3ull * MAXHW * 8 + 3 * MAXG * 8];

typedef unsigned long long ull;

__device__ __forceinline__ ull f2pk(float a, float b) {
    ull r; asm("mov.b64 %0,{%1,%2};" : "=l"(r) : "f"(a), "f"(b)); return r;
}
__device__ __forceinline__ float2 f2un(ull v) {
    float2 r; asm("mov.b64 {%0,%1},%2;" : "=f"(r.x), "=f"(r.y) : "l"(v)); return r;
}
__device__ __forceinline__ ull fma2(ull a, ull b, ull c) {
    ull r; asm("fma.rn.f32x2 %0,%1,%2,%3;" : "=l"(r) : "l"(a), "l"(b), "l"(c)); return r;
}
__device__ __forceinline__ ull mul2(ull a, ull b) {
    ull r; asm("mul.rn.f32x2 %0,%1,%2;" : "=l"(r) : "l"(a), "l"(b)); return r;
}
__device__ __forceinline__ ull add2(ull a, ull b) {
    ull r; asm("add.rn.f32x2 %0,%1,%2;" : "=l"(r) : "l"(a), "l"(b)); return r;
}

// ---------------- prep: interleave channels into 128B texels ----------------
__global__ void prep_kernel(const float* __restrict__ dp, const float* __restrict__ ap,
                            const float* __restrict__ dl, const float* __restrict__ al,
                            const float* __restrict__ denw, int G) {
    __shared__ float tile[32][129];
    int HW  = G * G;
    int ntp = (HW + 127) >> 7;
    int ntl = (G + 127) >> 7;
    int b = blockIdx.x;
    if (b < 3 * ntp) {
        int i = b / ntp, t = b - i * ntp;
        int p0 = t << 7;
        int np = min(128, HW - p0);
        for (int idx = threadIdx.x; idx < 32 * 128; idx += blockDim.x) {
            int ch = idx >> 7, p = idx & 127;
            float v = 0.f;
            if (p < np)
                v = (ch < 8) ? dp[(size_t)(i * 8 + ch) * HW + p0 + p]
                             : ap[(size_t)(i * 24 + ch - 8) * HW + p0 + p];
            tile[ch][p] = v;
        }
        __syncthreads();
        float* dst = (float*)(g_tex + ((size_t)i * MAXHW + p0) * 8);
        for (int idx = threadIdx.x; idx < np * 32; idx += blockDim.x) {
            int p = idx >> 5, ch = idx & 31;
            dst[idx] = tile[ch][p];
        }
    } else {
        b -= 3 * ntp;
        int i = b / ntl, t = b - i * ntl;
        int g0 = t << 7;
        int ng = min(128, G - g0);
        for (int idx = threadIdx.x; idx < 32 * 128; idx += blockDim.x) {
            int ch = idx >> 7, g = idx & 127;
            float v = 0.f;
            if (g < ng) {
                if (ch < 8) v = dl[(i * 8 + ch) * G + g0 + g] * denw[i * 8 + ch];
                else        v = al[(i * 24 + ch - 8) * G + g0 + g];
            }
            tile[ch][g] = v;
        }
        __syncthreads();
        float* dst = (float*)(g_tex + LTEX_OFF + ((size_t)i * MAXG + g0) * 8);
        for (int idx = threadIdx.x; idx < ng * 32; idx += blockDim.x) {
            int g = idx >> 5, ch = idx & 31;
            dst[idx] = tile[ch][g];
        }
    }
}

// ---------------- render ----------------
struct S1D { int i0, i1; float w; };

__device__ __forceinline__ S1D samp1d(float c, int G) {
    float f  = (c + 1.0f) * 0.5f * (float)(G - 1);
    float ff = floorf(f);
    S1D r;
    r.w = f - ff;                 // frac from UNclipped floor (matches ref)
    int i0 = (int)ff;
    i0 = min(max(i0, 0), G - 1);
    r.i0 = i0;
    r.i1 = min(i0 + 1, G - 1);
    return r;
}

#define NT 1024    // threads per CTA = 4 rays x 256 samples

__global__ __launch_bounds__(NT, 1)
void render_kernel(const float* __restrict__ xyz,
                   const float* __restrict__ zvals,
                   const float* __restrict__ appw,
                   const float* __restrict__ aabb,
                   float* __restrict__ out,
                   int Nr, int Ns, int G) {
    extern __shared__ float4 dsm[];
    // layout (float4 units first):
    float4* s_lines = dsm;                          // 3*G*8 f4   (lines, tight)
    float4* s_setA  = dsm + 3 * G * 8;              // NT*3 f4    (records)
    float4* s_setB  = s_setA + NT * 3;              // NT f4      (stw x3)
    float*  s_out   = (float*)(s_setB + NT);        // NT*4
    float*  s_z     = s_out + NT * 4;               // NT
    float*  s_A     = s_z + NT;                     // NT
    float*  s_B     = s_A + NT;                     // NT
    float*  s_part  = s_B + NT;                     // 32*3

    const int tid    = threadIdx.x;
    const int lane   = tid & 31;
    const int wrp    = tid >> 5;
    const int corner = lane >> 3;       // 0..3
    const int slot   = lane & 7;        // 0..7 (f4 index within texel)
    const bool pc1   = (corner & 1) != 0;
    const bool pc2   = (corner & 2) != 0;
    const bool isApp = (slot >= 2);
    const int  G8    = G * 8;           // y-step in f4 units

    const int rloc = tid >> 8;          // ray slot in CTA (0..3)
    int r = blockIdx.x * 4 + rloc;      // global ray
    const int rc = min(r, Nr - 1);      // clamped for loads
    const int s  = tid & 255;           // sample within ray

    // ---------- fill smem line texture (tight layout, texel = 8 f4) ----------
    {
        const float4* src = g_tex + LTEX_OFF;
        int nf4 = 3 * G8;
        for (int u = tid; u < nf4; u += NT) {
            int i   = u / G8;
            int rem = u - i * G8;
            s_lines[u] = src[i * (MAXG * 8) + rem];
        }
    }

    // packed appw rows 0-2 (zeros on density lanes); sigma via add2
    ull WA[3][3], WB[3][3];
#pragma unroll
    for (int rr = 0; rr < 3; rr++)
#pragma unroll
        for (int i = 0; i < 3; i++) {
            if (isApp) {
                float4 w = *(const float4*)(appw + rr * 72 + i * 24 + (slot - 2) * 4);
                WA[rr][i] = f2pk(w.x, w.y);
                WB[rr][i] = f2pk(w.z, w.w);
            } else {
                WA[rr][i] = 0ull; WB[rr][i] = 0ull;
            }
        }

    // ---------- setup: per-point sampling records ----------
    {
        size_t base = ((size_t)rc * Ns + s) * 3;
        float nc[3];
#pragma unroll
        for (int k = 0; k < 3; k++) {
            float lo = aabb[k], hi = aabb[3 + k];
            nc[k] = (xyz[base + k] - lo) * (2.0f / (hi - lo)) - 1.0f;
        }
        s_z[tid] = zvals[(size_t)rc * Ns + s];

        const int MA[3] = {0, 0, 1}, MB[3] = {1, 2, 2}, MV[3] = {2, 1, 0};
        float stw3[3];
#pragma unroll
        for (int i = 0; i < 3; i++) {
            S1D sx = samp1d(nc[MA[i]], G);
            S1D sy = samp1d(nc[MB[i]], G);
            S1D st = samp1d(nc[MV[i]], G);
            // u00: f4-unit index incl. plane base; A = u00<<2 | dyb<<1 | dxb
            int u00 = i * (MAXHW * 8) + (sy.i0 * G + sx.i0) * 8;
            int A = (u00 << 2) | ((sy.i1 - sy.i0) << 1) | (sx.i1 - sx.i0);
            // taps: line texel indices in TIGHT smem layout (i*G + tap)
            int T = (i * G + st.i0) | ((i * G + st.i1) << 16);
            s_setA[tid * 3 + i] = make_float4(
                __int_as_float(A), __int_as_float(T), sx.w, sy.w);
            stw3[i] = st.w;
        }
        s_setB[tid] = make_float4(stw3[0], stw3[1], stw3[2], 0.f);
    }
    __syncthreads();

    const ulonglong2* tb = (const ulonglong2*)g_tex + slot;      // slot folded
    const ulonglong2* lsm = (const ulonglong2*)s_lines + slot;   // smem lines

    // ---------- main pass: 32 points per warp ----------
    const int p0 = wrp << 5;
    for (int it = 0; it < 32; it++) {
        int p = p0 + it;
        float4 SB = s_setB[p];
        float stw3[3] = {SB.x, SB.y, SB.z};

        ull acc0 = 0ull, acc1 = 0ull, acc2 = 0ull, sacc = 0ull;
#pragma unroll
        for (int i = 0; i < 3; i++) {
            float4 SA = s_setA[p * 3 + i];
            int A = __float_as_int(SA.x);
            int T = __float_as_int(SA.y);
            float sxw = SA.z, syw = SA.w;

            int u    = (unsigned)A >> 2;
            int ux   = (A & 1) << 3;
            int uyv  = (A & 2) ? G8 : 0;
            int offu = u + (pc1 ? ux : 0) + (pc2 ? uyv : 0);
            int t0u  = (T & 0xFFFF) * 8;           // texel -> u2 units
            int t1u  = ((unsigned)T >> 16) * 8;

            ulonglong2 tex = __ldg(tb + offu);     // global (L2) corner texel
            ulonglong2 l0  = lsm[t0u];             // smem broadcast taps
            ulonglong2 l1  = lsm[t1u];

            float wc = (pc1 ? sxw : 1.f - sxw) * (pc2 ? syw : 1.f - syw);
            float s1 = wc * stw3[i];
            float s0 = wc - s1;
            ull s0p = f2pk(s0, s0);
            ull s1p = f2pk(s1, s1);

            ull gA = mul2(tex.x, fma2(l1.x, s1p, mul2(l0.x, s0p)));
            ull gB = mul2(tex.y, fma2(l1.y, s1p, mul2(l0.y, s0p)));

            acc0 = fma2(gB, WB[0][i], fma2(gA, WA[0][i], acc0));
            acc1 = fma2(gB, WB[1][i], fma2(gA, WA[1][i], acc1));
            acc2 = fma2(gB, WB[2][i], fma2(gA, WA[2][i], acc2));
            sacc = add2(sacc, add2(gA, gB));
        }
        float2 a0 = f2un(acc0);
        float2 a1 = f2un(acc1);
        float2 a2 = f2un(acc2);
        float2 a3 = f2un(sacc);
        float v0 = a0.x + a0.y;
        float v1 = a1.x + a1.y;
        float v2 = a2.x + a2.y;
        float v3 = isApp ? 0.f : (a3.x + a3.y);   // sigma: density lanes only

        // 6-shuffle 4-output butterfly reduce; row r lands on lanes (lane&3)==r
        const int b0 = lane & 1;
        const int b1 = lane & 2;
        float s1v = b0 ? v0 : v1;
        float r1  = __shfl_xor_sync(0xffffffffu, s1v, 1);
        float u0  = (b0 ? v1 : v0) + r1;           // row b0
        float s2v = b0 ? v2 : v3;
        float r2  = __shfl_xor_sync(0xffffffffu, s2v, 1);
        float u1  = (b0 ? v3 : v2) + r2;           // row 2+b0
        float s3v = b1 ? u0 : u1;
        float r3  = __shfl_xor_sync(0xffffffffu, s3v, 2);
        float wv  = (b1 ? u1 : u0) + r3;           // row lane&3
        wv += __shfl_xor_sync(0xffffffffu, wv, 4);
        wv += __shfl_xor_sync(0xffffffffu, wv, 8);
        wv += __shfl_xor_sync(0xffffffffu, wv, 16);
        if (lane < 4) s_out[p * 4 + lane] = wv;
    }
    __syncthreads();

    // ---------- per-ray alpha + transmittance scan -> weights ----------
    float w;
    {
        float sfeat = s_out[tid * 4 + 3] - 10.0f;
        float sigma = (sfeat > 15.0f) ? sfeat : log1pf(expf(sfeat));
        int zb = tid & ~255;    // ray base in CTA arrays
        float dist  = (s < Ns - 1) ? (s_z[tid + 1] - s_z[tid])
                                   : (s_z[zb + Ns - 1] - s_z[zb + Ns - 2]);
        float alpha = -expm1f(-sigma * (dist * 25.0f));
        s_A[tid] = 1.0f - alpha + 1e-10f;
        __syncthreads();
        float* cur = s_A;
        float* nxt = s_B;
        for (int off = 1; off < Ns; off <<= 1) {
            float v = cur[tid];
            if (s >= off) v *= cur[tid - off];
            nxt[tid] = v;
            __syncthreads();
            float* tmp = cur; cur = nxt; nxt = tmp;
        }
        float T = (s == 0) ? 1.0f : cur[tid - 1];
        w = alpha * T;
    }

    // ---------- weighted rgb sum (per ray: its 8 warps) ----------
    float q0 = w * s_out[tid * 4 + 0];
    float q1 = w * s_out[tid * 4 + 1];
    float q2 = w * s_out[tid * 4 + 2];
#pragma unroll
    for (int m = 16; m > 0; m >>= 1) {
        q0 += __shfl_xor_sync(0xffffffffu, q0, m);
        q1 += __shfl_xor_sync(0xffffffffu, q1, m);
        q2 += __shfl_xor_sync(0xffffffffu, q2, m);
    }
    if (lane == 0) {
        s_part[wrp * 3 + 0] = q0;
        s_part[wrp * 3 + 1] = q1;
        s_part[wrp * 3 + 2] = q2;
    }
    __syncthreads();
    if (s < 3 && r < Nr) {
        float sum = 0.f;
#pragma unroll
        for (int ww = 0; ww < 8; ww++) sum += s_part[(rloc * 8 + ww) * 3 + s];
        out[r * 3 + s] = sum;
    }
}

extern "C" void kernel_launch(void* const* d_in, const int* in_sizes, int n_in,
                              void* d_out, int out_size) {
    const float* xyz   = (const float*)d_in[0];
    const float* zvals = (const float*)d_in[2];
    const float* dp    = (const float*)d_in[3];
    const float* dl    = (const float*)d_in[4];
    const float* ap    = (const float*)d_in[5];
    const float* al    = (const float*)d_in[6];
    const float* denw  = (const float*)d_in[7];
    const float* appw  = (const float*)d_in[8];
    const float* aabb  = (const float*)d_in[9];

    int Nr = in_sizes[1] / 3;
    int Ns = in_sizes[2] / Nr;
    int G  = in_sizes[4] / 24;
    int HW = G * G;

    // dynamic smem: lines + records + setB + out/z/A/B/part
    size_t smem = (size_t)(3 * G * 8) * 16 + (size_t)NT * 3 * 16 + NT * 16
                + NT * 4 * 4 + NT * 4 * 3 + 32 * 3 * 4;
    cudaFuncSetAttribute(render_kernel,
                         cudaFuncAttributeMaxDynamicSharedMemorySize, (int)smem);

    int ntp = (HW + 127) / 128;
    int ntl = (G + 127) / 128;
    prep_kernel<<<3 * ntp + 3 * ntl, 256>>>(dp, ap, dl, al, denw, G);
    render_kernel<<<(Nr + 3) / 4, NT, smem>>>(xyz, zvals, appw, aabb,
                                              (float*)d_out, Nr, Ns, G);
}

// round 15
// speedup vs baseline: 1.0448x; 1.0448x over previous
#include <cuda_runtime.h>

// ---------------------------------------------------------------------------
// TensoRF slim renderer, v14 — v8 champion + L1D-protected streaming corners
//  + batched 9-load MLP + 3-row weight bank.
//  prep: combined 128B fp32 texels g_tex[i][HW][32ch] (ch0-7 density, basis
//        weights folded into LINE texture; ch8-31 appearance). Line texels
//        in the SAME array at LTEX_OFF.
//  render (block=ray, 256 thr, warp = 32 samples, 24KB smem, 3 CTAs/SM):
//    lane = corner*8 + slot. Per point: fetch all 3 plane records, unpack
//    addresses, then issue ALL 9 LDGs (corners via ld.global.nc.
//    L1::no_allocate so the random 34MB stream never evicts the 115KB line
//    textures from L1D; taps via normal __ldg -> ~100% L1 hits), then
//    packed f32x2 math; rows 0-2 via register appw; sigma via add2.
//    6-shuffle butterfly reduce -> (q0,q1,q2,sigma) per point.
//    Then alpha(-expm1) + smem product scan -> weights -> rgb reduce.
// ---------------------------------------------------------------------------

#define MAXG  320
#define MAXHW (MAXG * MAXG)
#define LTEX_OFF (3ull * MAXHW * 8)          // float4 units

__device__ float4 g_tex[3ull * MAXHW * 8 + 3 * MAXG * 8];

typedef unsigned long long ull;

__device__ __forceinline__ ull f2pk(float a, float b) {
    ull r; asm("mov.b64 %0,{%1,%2};" : "=l"(r) : "f"(a), "f"(b)); return r;
}
__device__ __forceinline__ float2 f2un(ull v) {
    float2 r; asm("mov.b64 {%0,%1},%2;" : "=f"(r.x), "=f"(r.y) : "l"(v)); return r;
}
__device__ __forceinline__ ull fma2(ull a, ull b, ull c) {
    ull r; asm("fma.rn.f32x2 %0,%1,%2,%3;" : "=l"(r) : "l"(a), "l"(b), "l"(c)); return r;
}
__device__ __forceinline__ ull mul2(ull a, ull b) {
    ull r; asm("mul.rn.f32x2 %0,%1,%2;" : "=l"(r) : "l"(a), "l"(b)); return r;
}
__device__ __forceinline__ ull add2(ull a, ull b) {
    ull r; asm("add.rn.f32x2 %0,%1,%2;" : "=l"(r) : "l"(a), "l"(b)); return r;
}
// streaming load: bypass L1 allocation (random-access corner texels)
__device__ __forceinline__ ulonglong2 ldg_na(const ulonglong2* p) {
    ulonglong2 v;
    asm("ld.global.nc.L1::no_allocate.v2.u64 {%0,%1}, [%2];"
        : "=l"(v.x), "=l"(v.y) : "l"(p));
    return v;
}

// ---------------- prep: interleave channels into 128B texels ----------------
__global__ void prep_kernel(const float* __restrict__ dp, const float* __restrict__ ap,
                            const float* __restrict__ dl, const float* __restrict__ al,
                            const float* __restrict__ denw, int G) {
    __shared__ float tile[32][129];
    int HW  = G * G;
    int ntp = (HW + 127) >> 7;
    int ntl = (G + 127) >> 7;
    int b = blockIdx.x;
    if (b < 3 * ntp) {
        int i = b / ntp, t = b - i * ntp;
        int p0 = t << 7;
        int np = min(128, HW - p0);
        for (int idx = threadIdx.x; idx < 32 * 128; idx += blockDim.x) {
            int ch = idx >> 7, p = idx & 127;
            float v = 0.f;
            if (p < np)
                v = (ch < 8) ? dp[(size_t)(i * 8 + ch) * HW + p0 + p]
                             : ap[(size_t)(i * 24 + ch - 8) * HW + p0 + p];
            tile[ch][p] = v;
        }
        __syncthreads();
        float* dst = (float*)(g_tex + ((size_t)i * MAXHW + p0) * 8);
        for (int idx = threadIdx.x; idx < np * 32; idx += blockDim.x) {
            int p = idx >> 5, ch = idx & 31;
            dst[idx] = tile[ch][p];
        }
    } else {
        b -= 3 * ntp;
        int i = b / ntl, t = b - i * ntl;
        int g0 = t << 7;
        int ng = min(128, G - g0);
        for (int idx = threadIdx.x; idx < 32 * 128; idx += blockDim.x) {
            int ch = idx >> 7, g = idx & 127;
            float v = 0.f;
            if (g < ng) {
                if (ch < 8) v = dl[(i * 8 + ch) * G + g0 + g] * denw[i * 8 + ch];
                else        v = al[(i * 24 + ch - 8) * G + g0 + g];
            }
            tile[ch][g] = v;
        }
        __syncthreads();
        float* dst = (float*)(g_tex + LTEX_OFF + ((size_t)i * MAXG + g0) * 8);
        for (int idx = threadIdx.x; idx < ng * 32; idx += blockDim.x) {
            int g = idx >> 5, ch = idx & 31;
            dst[idx] = tile[ch][g];
        }
    }
}

// ---------------- render ----------------
struct S1D { int i0, i1; float w; };

__device__ __forceinline__ S1D samp1d(float c, int G) {
    float f  = (c + 1.0f) * 0.5f * (float)(G - 1);
    float ff = floorf(f);
    S1D r;
    r.w = f - ff;                 // frac from UNclipped floor (matches ref)
    int i0 = (int)ff;
    i0 = min(max(i0, 0), G - 1);
    r.i0 = i0;
    r.i1 = min(i0 + 1, G - 1);
    return r;
}

__global__ __launch_bounds__(256, 3)
void render_kernel(const float* __restrict__ xyz,
                   const float* __restrict__ zvals,
                   const float* __restrict__ appw,
                   const float* __restrict__ aabb,
                   float* __restrict__ out,
                   int Ns, int G) {
    __shared__ float4 s_setA[256 * 3];  // per-pt per-plane (A, T, sxw, syw)
    __shared__ float4 s_setB[256];      // per-pt: stw x3
    __shared__ float  s_out[256 * 4];   // q0,q1,q2,sigma per point
    __shared__ float  s_z[256];
    __shared__ float  s_A[256];
    __shared__ float  s_B[256];
    __shared__ float  s_part[24];

    const int r      = blockIdx.x;
    const int tid    = threadIdx.x;
    const int lane   = tid & 31;
    const int wrp    = tid >> 5;
    const int corner = lane >> 3;       // 0..3
    const int slot   = lane & 7;        // 0..7 (f4 index within texel)
    const bool pc1   = (corner & 1) != 0;
    const bool pc2   = (corner & 2) != 0;
    const bool isApp = (slot >= 2);
    const int  G8    = G * 8;           // y-step in f4 units

    // packed appw rows 0-2 (zeros on density lanes); sigma via add2
    ull WA[3][3], WB[3][3];
#pragma unroll
    for (int rr = 0; rr < 3; rr++)
#pragma unroll
        for (int i = 0; i < 3; i++) {
            if (isApp) {
                float4 w = *(const float4*)(appw + rr * 72 + i * 24 + (slot - 2) * 4);
                WA[rr][i] = f2pk(w.x, w.y);
                WB[rr][i] = f2pk(w.z, w.w);
            } else {
                WA[rr][i] = 0ull; WB[rr][i] = 0ull;
            }
        }

    // ---------- setup: per-point sampling data ----------
    {
        size_t base = ((size_t)r * Ns + tid) * 3;
        float nc[3];
#pragma unroll
        for (int k = 0; k < 3; k++) {
            float lo = aabb[k], hi = aabb[3 + k];
            nc[k] = (xyz[base + k] - lo) * (2.0f / (hi - lo)) - 1.0f;
        }
        s_z[tid] = zvals[(size_t)r * Ns + tid];

        const int MA[3] = {0, 0, 1}, MB[3] = {1, 2, 2}, MV[3] = {2, 1, 0};
        float stw3[3];
#pragma unroll
        for (int i = 0; i < 3; i++) {
            S1D sx = samp1d(nc[MA[i]], G);
            S1D sy = samp1d(nc[MB[i]], G);
            S1D st = samp1d(nc[MV[i]], G);
            // u00: f4-unit index incl. plane base; A = u00<<2 | dyb<<1 | dxb
            int u00 = i * (MAXHW * 8) + (sy.i0 * G + sx.i0) * 8;
            int A = (u00 << 2) | ((sy.i1 - sy.i0) << 1) | (sx.i1 - sx.i0);
            // taps: f4-unit indices rel. to LTEX_OFF, 16-bit each
            int t0u = i * (MAXG * 8) + st.i0 * 8;
            int t1u = i * (MAXG * 8) + st.i1 * 8;
            int T = t0u | (t1u << 16);
            s_setA[tid * 3 + i] = make_float4(
                __int_as_float(A), __int_as_float(T), sx.w, sy.w);
            stw3[i] = st.w;
        }
        s_setB[tid] = make_float4(stw3[0], stw3[1], stw3[2], 0.f);
    }
    __syncthreads();

    const ulonglong2* tbp = (const ulonglong2*)g_tex + slot;            // slot folded
    const ulonglong2* lbp = (const ulonglong2*)g_tex + LTEX_OFF + slot;

    // ---------- main pass: 32 points per warp ----------
    const int p0 = wrp << 5;
    for (int it = 0; it < 32; it++) {
        int p = p0 + it;
        float4 SB = s_setB[p];
        float4 SA0 = s_setA[p * 3 + 0];
        float4 SA1 = s_setA[p * 3 + 1];
        float4 SA2 = s_setA[p * 3 + 2];

        // unpack addresses for all 3 planes
        int A0 = __float_as_int(SA0.x), T0 = __float_as_int(SA0.y);
        int A1 = __float_as_int(SA1.x), T1 = __float_as_int(SA1.y);
        int A2 = __float_as_int(SA2.x), T2 = __float_as_int(SA2.y);
        int off0 = ((unsigned)A0 >> 2) + (pc1 ? ((A0 & 1) << 3) : 0)
                 + (pc2 ? ((A0 & 2) ? G8 : 0) : 0);
        int off1 = ((unsigned)A1 >> 2) + (pc1 ? ((A1 & 1) << 3) : 0)
                 + (pc2 ? ((A1 & 2) ? G8 : 0) : 0);
        int off2 = ((unsigned)A2 >> 2) + (pc1 ? ((A2 & 1) << 3) : 0)
                 + (pc2 ? ((A2 & 2) ? G8 : 0) : 0);

        // batched loads: 9 in flight (corners streamed, taps L1-cached)
        ulonglong2 tex0 = ldg_na(tbp + off0);
        ulonglong2 tex1 = ldg_na(tbp + off1);
        ulonglong2 tex2 = ldg_na(tbp + off2);
        ulonglong2 l00  = __ldg(lbp + (T0 & 0xFFFF));
        ulonglong2 l01  = __ldg(lbp + ((unsigned)T0 >> 16));
        ulonglong2 l10  = __ldg(lbp + (T1 & 0xFFFF));
        ulonglong2 l11  = __ldg(lbp + ((unsigned)T1 >> 16));
        ulonglong2 l20  = __ldg(lbp + (T2 & 0xFFFF));
        ulonglong2 l21  = __ldg(lbp + ((unsigned)T2 >> 16));

        // scalar weights while loads are in flight
        float wc0 = (pc1 ? SA0.z : 1.f - SA0.z) * (pc2 ? SA0.w : 1.f - SA0.w);
        float wc1 = (pc1 ? SA1.z : 1.f - SA1.z) * (pc2 ? SA1.w : 1.f - SA1.w);
        float wc2 = (pc1 ? SA2.z : 1.f - SA2.z) * (pc2 ? SA2.w : 1.f - SA2.w);
        float s1a = wc0 * SB.x, s0a = wc0 - s1a;
        float s1b = wc1 * SB.y, s0b = wc1 - s1b;
        float s1c = wc2 * SB.z, s0c = wc2 - s1c;

        ull acc0, acc1, acc2, sacc;
        {
            ull s0p = f2pk(s0a, s0a), s1p = f2pk(s1a, s1a);
            ull gA = mul2(tex0.x, fma2(l01.x, s1p, mul2(l00.x, s0p)));
            ull gB = mul2(tex0.y, fma2(l01.y, s1p, mul2(l00.y, s0p)));
            acc0 = fma2(gB, WB[0][0], mul2(gA, WA[0][0]));
            acc1 = fma2(gB, WB[1][0], mul2(gA, WA[1][0]));
            acc2 = fma2(gB, WB[2][0], mul2(gA, WA[2][0]));
            sacc = add2(gA, gB);
        }
        {
            ull s0p = f2pk(s0b, s0b), s1p = f2pk(s1b, s1b);
            ull gA = mul2(tex1.x, fma2(l11.x, s1p, mul2(l10.x, s0p)));
            ull gB = mul2(tex1.y, fma2(l11.y, s1p, mul2(l10.y, s0p)));
            acc0 = fma2(gB, WB[0][1], fma2(gA, WA[0][1], acc0));
            acc1 = fma2(gB, WB[1][1], fma2(gA, WA[1][1], acc1));
            acc2 = fma2(gB, WB[2][1], fma2(gA, WA[2][1], acc2));
            sacc = add2(sacc, add2(gA, gB));
        }
        {
            ull s0p = f2pk(s0c, s0c), s1p = f2pk(s1c, s1c);
            ull gA = mul2(tex2.x, fma2(l21.x, s1p, mul2(l20.x, s0p)));
            ull gB = mul2(tex2.y, fma2(l21.y, s1p, mul2(l20.y, s0p)));
            acc0 = fma2(gB, WB[0][2], fma2(gA, WA[0][2], acc0));
            acc1 = fma2(gB, WB[1][2], fma2(gA, WA[1][2], acc1));
            acc2 = fma2(gB, WB[2][2], fma2(gA, WA[2][2], acc2));
            sacc = add2(sacc, add2(gA, gB));
        }

        float2 a0 = f2un(acc0);
        float2 a1 = f2un(acc1);
        float2 a2 = f2un(acc2);
        float2 a3 = f2un(sacc);
        float v0 = a0.x + a0.y;
        float v1 = a1.x + a1.y;
        float v2 = a2.x + a2.y;
        float v3 = isApp ? 0.f : (a3.x + a3.y);   // sigma: density lanes only

        // 6-shuffle 4-output butterfly reduce; row r lands on lanes (lane&3)==r
        const int b0 = lane & 1;
        const int b1 = lane & 2;
        float s1v = b0 ? v0 : v1;
        float r1  = __shfl_xor_sync(0xffffffffu, s1v, 1);
        float u0  = (b0 ? v1 : v0) + r1;           // row b0
        float s2v = b0 ? v2 : v3;
        float r2  = __shfl_xor_sync(0xffffffffu, s2v, 1);
        float u1  = (b0 ? v3 : v2) + r2;           // row 2+b0
        float s3v = b1 ? u0 : u1;
        float r3  = __shfl_xor_sync(0xffffffffu, s3v, 2);
        float wv  = (b1 ? u1 : u0) + r3;           // row lane&3
        wv += __shfl_xor_sync(0xffffffffu, wv, 4);
        wv += __shfl_xor_sync(0xffffffffu, wv, 8);
        wv += __shfl_xor_sync(0xffffffffu, wv, 16);
        if (lane < 4) s_out[p * 4 + lane] = wv;
    }
    __syncthreads();

    // ---------- alpha + transmittance scan -> weights ----------
    float w;
    {
        float sfeat = s_out[tid * 4 + 3] - 10.0f;
        float sigma = (sfeat > 15.0f) ? sfeat : log1pf(expf(sfeat));
        float dist  = (tid < Ns - 1) ? (s_z[tid + 1] - s_z[tid])
                                     : (s_z[Ns - 1] - s_z[Ns - 2]);
        float alpha = -expm1f(-sigma * (dist * 25.0f));
        s_A[tid] = 1.0f - alpha + 1e-10f;
        __syncthreads();
        float* cur = s_A;
        float* nxt = s_B;
        for (int off = 1; off < Ns; off <<= 1) {
            float v = cur[tid];
            if (tid >= off) v *= cur[tid - off];
            nxt[tid] = v;
            __syncthreads();
            float* tmp = cur; cur = nxt; nxt = tmp;
        }
        float T = (tid == 0) ? 1.0f : cur[tid - 1];
        w = alpha * T;
    }

    // ---------- weighted rgb sum ----------
    float q0 = w * s_out[tid * 4 + 0];
    float q1 = w * s_out[tid * 4 + 1];
    float q2 = w * s_out[tid * 4 + 2];
#pragma unroll
    for (int m = 16; m > 0; m >>= 1) {
        q0 += __shfl_xor_sync(0xffffffffu, q0, m);
        q1 += __shfl_xor_sync(0xffffffffu, q1, m);
        q2 += __shfl_xor_sync(0xffffffffu, q2, m);
    }
    if (lane == 0) {
        s_part[wrp * 3 + 0] = q0;
        s_part[wrp * 3 + 1] = q1;
        s_part[wrp * 3 + 2] = q2;
    }
    __syncthreads();
    if (tid < 3) {
        float sum = 0.f;
#pragma unroll
        for (int ww = 0; ww < 8; ww++) sum += s_part[ww * 3 + tid];
        out[r * 3 + tid] = sum;
    }
}

extern "C" void kernel_launch(void* const* d_in, const int* in_sizes, int n_in,
                              void* d_out, int out_size) {
    const float* xyz   = (const float*)d_in[0];
    const float* zvals = (const float*)d_in[2];
    const float* dp    = (const float*)d_in[3];
    const float* dl    = (const float*)d_in[4];
    const float* ap    = (const float*)d_in[5];
    const float* al    = (const float*)d_in[6];
    const float* denw  = (const float*)d_in[7];
    const float* appw  = (const float*)d_in[8];
    const float* aabb  = (const float*)d_in[9];

    int Nr = in_sizes[1] / 3;
    int Ns = in_sizes[2] / Nr;
    int G  = in_sizes[4] / 24;
    int HW = G * G;

    int ntp = (HW + 127) / 128;
    int ntl = (G + 127) / 128;
    prep_kernel<<<3 * ntp + 3 * ntl, 256>>>(dp, ap, dl, al, denw, G);
    render_kernel<<<Nr, Ns>>>(xyz, zvals, appw, aabb, (float*)d_out, Ns, G);
}